// round 1
// baseline (speedup 1.0000x reference)
#include <cuda_runtime.h>
#include <math.h>

// ModulatedConv2D: y = sigma[b,o] * conv2d_same(x * style[b,i], GAIN*weight)
// sigma[b,o] = rsqrt(GAIN^2 * sum_i style[b,i]^2 * sum_k w[o,i,k]^2 + eps)
//
// Shapes: x[16,512,32,32], style[16,512], weight[512,512,3,3] -> out[16,512,32,32]

#define B     16
#define C     512
#define HW    32
#define KK    9          // 3x3
#define RK    (C * KK)   // 4608 reduction length
#define EPSV  1e-8f

static __device__ float g_wT[RK * C];     // wT[(ic*9+k)*512 + oc] = GAIN * weight[oc][ic][k]
static __device__ float g_wsq[C * C];     // wsq[oc*512 + ic] = sum_k (GAIN*w)^2
static __device__ float g_sigma[B * C];   // demod factors

// ---------------------------------------------------------------------------
// Kernel 1: weight transpose (+GAIN) and per-(oc,ic) squared sums
// grid (8 oc-tiles, 64 ic-tiles), 256 threads
// ---------------------------------------------------------------------------
__global__ void prep_kernel(const float* __restrict__ weight, float gain) {
    const int oc0 = blockIdx.x * 64;
    const int ic0 = blockIdx.y * 8;
    __shared__ float sw[64][73];   // pad to 73 to avoid bank conflicts

    // coalesced-ish read: each oc row is 72 contiguous floats
    for (int idx = threadIdx.x; idx < 64 * 72; idx += 256) {
        int o = idx / 72, ik = idx % 72;
        sw[o][ik] = weight[(size_t)(oc0 + o) * RK + ic0 * 9 + ik] * gain;
    }
    __syncthreads();

    // coalesced write of wT rows (64 consecutive oc)
    for (int idx = threadIdx.x; idx < 64 * 72; idx += 256) {
        int o = idx & 63, ik = idx >> 6;
        g_wT[(size_t)(ic0 * 9 + ik) * C + oc0 + o] = sw[o][ik];
    }

    // squared sums
    for (int idx = threadIdx.x; idx < 64 * 8; idx += 256) {
        int o = idx >> 3, i = idx & 7;
        float s = 0.f;
#pragma unroll
        for (int k = 0; k < 9; ++k) { float v = sw[o][i * 9 + k]; s += v * v; }
        g_wsq[(oc0 + o) * C + ic0 + i] = s;
    }
}

// ---------------------------------------------------------------------------
// Kernel 2: sigma[b,oc] = rsqrt(sum_i style^2 * wsq + eps)
// grid (64, 16), 256 threads; one warp per oc
// ---------------------------------------------------------------------------
__global__ void sigma_kernel(const float* __restrict__ style) {
    const int b    = blockIdx.y;
    const int warp = threadIdx.x >> 5;
    const int lane = threadIdx.x & 31;
    const int oc   = blockIdx.x * 8 + warp;

    float v = 0.f;
    for (int i = lane; i < C; i += 32) {
        float s = style[b * C + i];
        v += s * s * g_wsq[oc * C + i];
    }
#pragma unroll
    for (int off = 16; off; off >>= 1)
        v += __shfl_xor_sync(0xffffffffu, v, off);
    if (lane == 0)
        g_sigma[b * C + oc] = rsqrtf(v + EPSV);
}

// ---------------------------------------------------------------------------
// Kernel 3: the conv.
// grid (4 row-tiles, 8 oc-tiles, 16 batch), 256 threads.
// Block tile: 64 oc x 8 rows x 32 cols. ic chunked by 8.
// Thread: og = tid/64 (16 oc), pg = tid%64 -> 4 pixels (col = pg&31,
// rows = 2q + (pg>>5)). 64 fp32 accumulators per thread.
// ---------------------------------------------------------------------------
__global__ void __launch_bounds__(256, 2)
conv_kernel(const float* __restrict__ x, const float* __restrict__ style,
            float* __restrict__ out) {
    const int b   = blockIdx.z;
    const int oc0 = blockIdx.y * 64;
    const int r0  = blockIdx.x * 8;
    const int tid = threadIdx.x;

    const int og    = tid >> 6;        // 0..3  (oc group of 16)
    const int pg    = tid & 63;        // 0..63 (pixel group)
    const int col   = pg & 31;         // output column
    const int rbase = pg >> 5;         // 0 or 1

    __shared__ float xs[8][10][34];    // [ic][row(+halo)][col(+halo)]
    __shared__ float ws[72][64];       // [(ic*9+k)][oc]

    float acc[16][4];
#pragma unroll
    for (int j = 0; j < 16; ++j)
#pragma unroll
        for (int q = 0; q < 4; ++q) acc[j][q] = 0.f;

    const float* xb = x + (size_t)b * C * (HW * HW);

    for (int ic0 = 0; ic0 < C; ic0 += 8) {
        __syncthreads();
        // --- load weight tile (coalesced from transposed layout) ---
        for (int idx = tid; idx < 72 * 64; idx += 256) {
            int o = idx & 63, ik = idx >> 6;
            ws[ik][o] = g_wT[(size_t)(ic0 * 9 + ik) * C + oc0 + o];
        }
        // --- load x tile with halo, modulated by style ---
        for (int idx = tid; idx < 8 * 10 * 34; idx += 256) {
            int cc = idx % 34;
            int t2 = idx / 34;
            int rr = t2 % 10;
            int ic = t2 / 10;
            int row = r0 - 1 + rr;
            int c   = cc - 1;
            float v = 0.f;
            if ((unsigned)row < 32u && (unsigned)c < 32u)
                v = xb[(ic0 + ic) * (HW * HW) + row * HW + c] *
                    style[b * C + ic0 + ic];
            xs[ic][rr][cc] = v;
        }
        __syncthreads();

        // --- compute ---
#pragma unroll 1
        for (int ic = 0; ic < 8; ++ic) {
#pragma unroll
            for (int k = 0; k < 9; ++k) {
                const int kh = k / 3, kw = k % 3;
                float xv[4];
#pragma unroll
                for (int q = 0; q < 4; ++q)
                    xv[q] = xs[ic][rbase + 2 * q + kh][col + kw];
                const float4* wp =
                    reinterpret_cast<const float4*>(&ws[ic * 9 + k][og * 16]);
#pragma unroll
                for (int v4 = 0; v4 < 4; ++v4) {
                    float4 w = wp[v4];
#pragma unroll
                    for (int q = 0; q < 4; ++q) {
                        acc[v4 * 4 + 0][q] += w.x * xv[q];
                        acc[v4 * 4 + 1][q] += w.y * xv[q];
                        acc[v4 * 4 + 2][q] += w.z * xv[q];
                        acc[v4 * 4 + 3][q] += w.w * xv[q];
                    }
                }
            }
        }
    }

    // --- epilogue: demodulate + store ---
#pragma unroll
    for (int j = 0; j < 16; ++j) {
        const int oc = oc0 + og * 16 + j;
        const float sg = g_sigma[b * C + oc];
        float* op = out + ((size_t)b * C + oc) * (HW * HW);
#pragma unroll
        for (int q = 0; q < 4; ++q) {
            int row = r0 + 2 * q + rbase;
            op[row * HW + col] = acc[j][q] * sg;
        }
    }
}

// ---------------------------------------------------------------------------
extern "C" void kernel_launch(void* const* d_in, const int* in_sizes, int n_in,
                              void* d_out, int out_size) {
    const float* x      = (const float*)d_in[0];
    const float* style  = (const float*)d_in[1];
    const float* weight = (const float*)d_in[2];
    float* out          = (float*)d_out;
    (void)in_sizes; (void)n_in; (void)out_size;

    const float gain = 1.0f / sqrtf((float)(C * KK));  // 1/sqrt(4608)

    prep_kernel<<<dim3(8, 64), 256>>>(weight, gain);
    sigma_kernel<<<dim3(64, 16), 256>>>(style);
    conv_kernel<<<dim3(4, 8, 16), 256>>>(x, style, out);
}

// round 8
// speedup vs baseline: 2.6786x; 2.6786x over previous
#include <cuda_runtime.h>
#include <cuda_fp16.h>
#include <cstdint>
#include <math.h>

// ModulatedConv2D via mma.sync (fp16 hi/lo split, fp32 accum) implicit GEMM.
// y = sigma[b,o] * conv2d_same(x * style[b,i], GAIN*weight)
// x[16,512,32,32], style[16,512], weight[512,512,3,3] -> out[16,512,32,32]

#define NB 16
#define NC 512
#define HW2 1024
#define EPSV 1e-8f
#define NCHUNK 144   // 16 ic-chunks * 9 taps, K=32 each

static __device__ float g_wsq[NC * NC];
static __device__ float g_sigma[NB * NC];
// pre-split weight tiles: [octile(4)][chunk(144)] -> hi[128oc][32k] fp16 (8KB), lo (8KB)
static __device__ unsigned char g_btiles[(size_t)4 * NCHUNK * 16384];

// ---------------------------------------------------------------------------
__device__ __forceinline__ uint32_t smem_u32(const void* p) {
    uint32_t a;
    asm("{ .reg .u64 t; cvta.to.shared.u64 t, %1; cvt.u32.u64 %0, t; }"
        : "=r"(a) : "l"(p));
    return a;
}
#define CP_ASYNC16(dst, src) \
    asm volatile("cp.async.cg.shared.global [%0], [%1], 16;" :: "r"(dst), "l"(src))
#define CP_COMMIT() asm volatile("cp.async.commit_group;")
#define CP_WAIT0()  asm volatile("cp.async.wait_group 0;" ::: "memory")

#define LDMX4(r, addr) \
    asm volatile("ldmatrix.sync.aligned.m8n8.x4.shared.b16 {%0,%1,%2,%3}, [%4];" \
                 : "=r"((r)[0]), "=r"((r)[1]), "=r"((r)[2]), "=r"((r)[3]) : "r"(addr))
#define LDMX2(r, addr) \
    asm volatile("ldmatrix.sync.aligned.m8n8.x2.shared.b16 {%0,%1}, [%2];" \
                 : "=r"((r)[0]), "=r"((r)[1]) : "r"(addr))

#define MMA16816(d, a, b) \
    asm volatile("mma.sync.aligned.m16n8k16.row.col.f32.f16.f16.f32 " \
                 "{%0,%1,%2,%3}, {%4,%5,%6,%7}, {%8,%9}, {%0,%1,%2,%3};" \
                 : "+f"((d)[0]), "+f"((d)[1]), "+f"((d)[2]), "+f"((d)[3]) \
                 : "r"((a)[0]), "r"((a)[1]), "r"((a)[2]), "r"((a)[3]), \
                   "r"((b)[0]), "r"((b)[1]))

// ---------------------------------------------------------------------------
// wsq[oc,ic] = sum_k (GAIN*w)^2
// ---------------------------------------------------------------------------
__global__ void wsq_kernel(const float* __restrict__ weight, float gain) {
    const int oc0 = blockIdx.x * 64;
    const int ic0 = blockIdx.y * 8;
    __shared__ float sw[64][73];
    for (int idx = threadIdx.x; idx < 64 * 72; idx += 256) {
        int o = idx / 72, ik = idx % 72;
        sw[o][ik] = weight[(size_t)(oc0 + o) * 4608 + ic0 * 9 + ik] * gain;
    }
    __syncthreads();
    for (int idx = threadIdx.x; idx < 64 * 8; idx += 256) {
        int o = idx >> 3, i = idx & 7;
        float s = 0.f;
#pragma unroll
        for (int k = 0; k < 9; ++k) { float v = sw[o][i * 9 + k]; s += v * v; }
        g_wsq[(oc0 + o) * NC + ic0 + i] = s;
    }
}

__global__ void sigma_kernel(const float* __restrict__ style) {
    const int b = blockIdx.y;
    const int warp = threadIdx.x >> 5, lane = threadIdx.x & 31;
    const int oc = blockIdx.x * 8 + warp;
    float v = 0.f;
    for (int i = lane; i < NC; i += 32) {
        float s = style[b * NC + i];
        v += s * s * g_wsq[oc * NC + i];
    }
#pragma unroll
    for (int off = 16; off; off >>= 1) v += __shfl_xor_sync(0xffffffffu, v, off);
    if (lane == 0) g_sigma[b * NC + oc] = rsqrtf(v + EPSV);
}

// ---------------------------------------------------------------------------
// prep: weights -> hi/lo fp16 tiles, layout [oc(128)][k(32)] packed 64B rows.
// grid (144, 4), 256 threads: thread = (oc 0..127) x (khalf 0..1)
// ---------------------------------------------------------------------------
__global__ void prep_b(const float* __restrict__ weight, float gain) {
    const int cc = blockIdx.x, octile = blockIdx.y;
    const int icch = cc / 9, tap = cc % 9;
    const int ocl = threadIdx.x >> 1;
    const int kh = (threadIdx.x & 1) * 16;
    const int oc = octile * 128 + ocl;
    const float* wr = weight + (size_t)oc * 4608 + (size_t)(icch * 32 + kh) * 9 + tap;
    union { __half2 h2[8]; uint4 u4[2]; } H, L;
#pragma unroll
    for (int j = 0; j < 8; ++j) {
        float v0 = wr[(2 * j) * 9] * gain;
        float v1 = wr[(2 * j + 1) * 9] * gain;
        __half h0 = __float2half(v0), h1 = __float2half(v1);
        __half l0 = __float2half(v0 - __half2float(h0));
        __half l1 = __float2half(v1 - __half2float(h1));
        H.h2[j] = __halves2half2(h0, h1);
        L.h2[j] = __halves2half2(l0, l1);
    }
    unsigned char* blk = g_btiles + (size_t)(octile * NCHUNK + cc) * 16384;
    uint4* dh = (uint4*)(blk + ocl * 64 + kh * 2);
    uint4* dl = (uint4*)(blk + 8192 + ocl * 64 + kh * 2);
    dh[0] = H.u4[0]; dh[1] = H.u4[1];
    dl[0] = L.u4[0]; dl[1] = L.u4[1];
}

// ---------------------------------------------------------------------------
// conv: grid (8 pixtiles, 4 octiles, 16 b), 256 threads (8 warps).
// CTA tile: M=128 oc x N=128 pix, K-chunk 32.
// smem stage (40960B): WH[128][40]h 10240 | WL 10240 | XH 10240 | XL 10240
// stages at 0 / 40960 ; s_sig @81920 (512B) ; s_sty @82432 (2048B)
// ---------------------------------------------------------------------------
#define RS 80u          // row stride bytes (40 halves)
#define ST_WH 0u
#define ST_WL 10240u
#define ST_XH 20480u
#define ST_XL 30720u
#define STAGE 40960u
#define SM_TOTAL 84480

__global__ void __launch_bounds__(256, 2)
conv_mma(const float* __restrict__ x, const float* __restrict__ style,
         float* __restrict__ out) {
    extern __shared__ char smem[];
    const uint32_t sb = smem_u32(smem);
    const int tid = threadIdx.x;
    const int lane = tid & 31, wid = tid >> 5;
    const int wm = wid & 1;        // m warp (oc): 0..1 -> offset wm*64
    const int wn = wid >> 1;       // n warp (pix): 0..3 -> offset wn*32
    const int pixtile = blockIdx.x, octile = blockIdx.y, b = blockIdx.z;

    float* s_sig = (float*)(smem + 81920);
    float* s_sty = (float*)(smem + 82432);
    for (int i = tid; i < 128; i += 256) s_sig[i] = g_sigma[b * NC + octile * 128 + i];
    for (int i = tid; i < NC; i += 256) s_sty[i] = style[b * NC + i];
    __syncthreads();   // <<< FIX: s_sty written by other warps is read in the
                       //     prologue's storeX below; without this sync chunk 0
                       //     was modulated with garbage (rel_err 2.7e-2).

    const float* xb = x + (size_t)b * NC * HW2;
    const unsigned char* wbase = g_btiles + (size_t)octile * NCHUNK * 16384;

    // per-thread build coords: p = pixel row in tile, khf = k half (0/16)
    const int p = tid >> 1;
    const int khf = (tid & 1) * 16;
    const int pr = pixtile * 4 + (p >> 5);   // image row of this pixel
    const int pc = p & 31;                   // image col

    // ldmatrix per-lane offsets
    const uint32_t aoff = (uint32_t)(lane & 15) * RS + (uint32_t)(lane >> 4) * 16u;
    const uint32_t boff = (uint32_t)(lane & 7) * RS + (uint32_t)((lane >> 3) & 1) * 16u;

    float acc[4][4][4];
#pragma unroll
    for (int m = 0; m < 4; ++m)
#pragma unroll
        for (int n = 0; n < 4; ++n)
#pragma unroll
            for (int r = 0; r < 4; ++r) acc[m][n][r] = 0.f;

    // ---- helpers as lambdas ----
    auto issueW = [&](int c, uint32_t stb) {
        const unsigned char* src = wbase + (size_t)c * 16384;
#pragma unroll
        for (int j = 0; j < 2; ++j) {
            int cidx = tid + j * 256;               // 0..511 16B chunks
            int row = cidx >> 2, off = cidx & 3;
            CP_ASYNC16(sb + stb + ST_WH + row * RS + off * 16, src + cidx * 16);
            CP_ASYNC16(sb + stb + ST_WL + row * RS + off * 16, src + 8192 + cidx * 16);
        }
        CP_COMMIT();
    };
    auto prefX = [&](int c, float* xv) {
        const int icch = c / 9, tap = c - icch * 9;
        const int sr = pr + tap / 3 - 1, sc = pc + tap % 3 - 1;
        const bool inb = ((unsigned)sr < 32u) && ((unsigned)sc < 32u);
        const float* xp = xb + ((size_t)(icch * 32 + khf) << 10) +
                          (inb ? (sr * 32 + sc) : 0);
#pragma unroll
        for (int j = 0; j < 16; ++j) xv[j] = inb ? xp[(size_t)j << 10] : 0.f;
    };
    auto storeX = [&](int c, uint32_t stb, const float* xv) {
        const int icch = c / 9;
        const int styb = icch * 32 + khf;
        union { __half2 h2[8]; uint4 u4[2]; } H, L;
#pragma unroll
        for (int j = 0; j < 8; ++j) {
            float v0 = xv[2 * j] * s_sty[styb + 2 * j];
            float v1 = xv[2 * j + 1] * s_sty[styb + 2 * j + 1];
            __half h0 = __float2half(v0), h1 = __float2half(v1);
            __half l0 = __float2half(v0 - __half2float(h0));
            __half l1 = __float2half(v1 - __half2float(h1));
            H.h2[j] = __halves2half2(h0, h1);
            L.h2[j] = __halves2half2(l0, l1);
        }
        uint4* dh = (uint4*)(smem + stb + ST_XH + p * RS + khf * 2);
        uint4* dl = (uint4*)(smem + stb + ST_XL + p * RS + khf * 2);
        dh[0] = H.u4[0]; dh[1] = H.u4[1];
        dl[0] = L.u4[0]; dl[1] = L.u4[1];
    };

    // ---- prologue: chunk 0 ----
    {
        issueW(0, 0);
        float xv[16];
        prefX(0, xv);
        storeX(0, 0, xv);
        CP_WAIT0();
        __syncthreads();
    }

    // ---- main loop ----
#pragma unroll 1
    for (int c = 0; c < NCHUNK; ++c) {
        const uint32_t stb = (uint32_t)(c & 1) * STAGE;
        const uint32_t nstb = stb ^ STAGE;
        float xv[16];
        if (c + 1 < NCHUNK) {
            issueW(c + 1, nstb);
            prefX(c + 1, xv);
        }
        // MMA over stage stb
#pragma unroll
        for (int ks = 0; ks < 2; ++ks) {
            const uint32_t kb = (uint32_t)ks * 32u;
            uint32_t ah[4][4], bh[4][2], bl[4][2], al[4][4];
#pragma unroll
            for (int m = 0; m < 4; ++m)
                LDMX4(ah[m], sb + stb + ST_WH + (uint32_t)(wm * 64 + m * 16) * RS + kb + aoff);
#pragma unroll
            for (int n = 0; n < 4; ++n)
                LDMX2(bh[n], sb + stb + ST_XH + (uint32_t)(wn * 32 + n * 8) * RS + kb + boff);
#pragma unroll
            for (int m = 0; m < 4; ++m)
#pragma unroll
                for (int n = 0; n < 4; ++n) MMA16816(acc[m][n], ah[m], bh[n]);
#pragma unroll
            for (int n = 0; n < 4; ++n)
                LDMX2(bl[n], sb + stb + ST_XL + (uint32_t)(wn * 32 + n * 8) * RS + kb + boff);
#pragma unroll
            for (int m = 0; m < 4; ++m)
#pragma unroll
                for (int n = 0; n < 4; ++n) MMA16816(acc[m][n], ah[m], bl[n]);
#pragma unroll
            for (int m = 0; m < 4; ++m)
                LDMX4(al[m], sb + stb + ST_WL + (uint32_t)(wm * 64 + m * 16) * RS + kb + aoff);
#pragma unroll
            for (int m = 0; m < 4; ++m)
#pragma unroll
                for (int n = 0; n < 4; ++n) MMA16816(acc[m][n], al[m], bh[n]);
        }
        if (c + 1 < NCHUNK) {
            storeX(c + 1, nstb, xv);
            CP_WAIT0();
        }
        __syncthreads();
    }

    // ---- epilogue: demodulate + store (float2, coalesced-ish) ----
    float* ob = out + (size_t)b * NC * HW2 + (size_t)octile * 128 * HW2 +
                pixtile * 128;
#pragma unroll
    for (int m = 0; m < 4; ++m) {
        const int r0 = wm * 64 + m * 16 + (lane >> 2);
        const float sg0 = s_sig[r0], sg1 = s_sig[r0 + 8];
#pragma unroll
        for (int n = 0; n < 4; ++n) {
            const int col = wn * 32 + n * 8 + (lane & 3) * 2;
            float2 v0 = make_float2(acc[m][n][0] * sg0, acc[m][n][1] * sg0);
            float2 v1 = make_float2(acc[m][n][2] * sg1, acc[m][n][3] * sg1);
            *(float2*)(ob + (size_t)r0 * HW2 + col) = v0;
            *(float2*)(ob + (size_t)(r0 + 8) * HW2 + col) = v1;
        }
    }
}

// ---------------------------------------------------------------------------
extern "C" void kernel_launch(void* const* d_in, const int* in_sizes, int n_in,
                              void* d_out, int out_size) {
    const float* x      = (const float*)d_in[0];
    const float* style  = (const float*)d_in[1];
    const float* weight = (const float*)d_in[2];
    float* out          = (float*)d_out;
    (void)in_sizes; (void)n_in; (void)out_size;

    const float gain = 1.0f / sqrtf(4608.0f);

    cudaFuncSetAttribute(conv_mma, cudaFuncAttributeMaxDynamicSharedMemorySize,
                         SM_TOTAL);

    wsq_kernel<<<dim3(8, 64), 256>>>(weight, gain);
    prep_b<<<dim3(NCHUNK, 4), 256>>>(weight, gain);
    sigma_kernel<<<dim3(64, 16), 256>>>(style);
    conv_mma<<<dim3(8, 4, 16), 256, SM_TOTAL>>>(x, style, out);
}

// round 9
// speedup vs baseline: 3.8600x; 1.4410x over previous
#include <cuda_runtime.h>
#include <cuda_fp16.h>
#include <cstdint>
#include <math.h>

// ModulatedConv2D via mma.sync (fp16 split: w_hi*(x_hi+x_lo)) implicit GEMM.
// y = sigma[b,o] * conv2d_same(x * style[b,i], GAIN*weight)
// x[16,512,32,32], style[16,512], weight[512,512,3,3] -> out[16,512,32,32]

#define NB 16
#define NC 512
#define HW2 1024
#define EPSV 1e-8f
#define NCHUNK 144   // 16 ic-chunks * 9 taps, K=32 each

static __device__ float g_wsq[NC * NC];
static __device__ float g_sigma[NB * NC];
// weight tiles (hi only): [octile(4)][chunk(144)] -> hi[128oc][32k] fp16 (8KB)
static __device__ unsigned char g_btiles[(size_t)4 * NCHUNK * 8192];

// ---------------------------------------------------------------------------
__device__ __forceinline__ uint32_t smem_u32(const void* p) {
    uint32_t a;
    asm("{ .reg .u64 t; cvta.to.shared.u64 t, %1; cvt.u32.u64 %0, t; }"
        : "=r"(a) : "l"(p));
    return a;
}
#define CP_ASYNC16(dst, src) \
    asm volatile("cp.async.cg.shared.global [%0], [%1], 16;" :: "r"(dst), "l"(src))
#define CP_COMMIT() asm volatile("cp.async.commit_group;")
#define CP_WAIT0()  asm volatile("cp.async.wait_group 0;" ::: "memory")

#define LDMX4(r, addr) \
    asm volatile("ldmatrix.sync.aligned.m8n8.x4.shared.b16 {%0,%1,%2,%3}, [%4];" \
                 : "=r"((r)[0]), "=r"((r)[1]), "=r"((r)[2]), "=r"((r)[3]) : "r"(addr))
#define LDMX2(r, addr) \
    asm volatile("ldmatrix.sync.aligned.m8n8.x2.shared.b16 {%0,%1}, [%2];" \
                 : "=r"((r)[0]), "=r"((r)[1]) : "r"(addr))

#define MMA16816(d, a, b) \
    asm volatile("mma.sync.aligned.m16n8k16.row.col.f32.f16.f16.f32 " \
                 "{%0,%1,%2,%3}, {%4,%5,%6,%7}, {%8,%9}, {%0,%1,%2,%3};" \
                 : "+f"((d)[0]), "+f"((d)[1]), "+f"((d)[2]), "+f"((d)[3]) \
                 : "r"((a)[0]), "r"((a)[1]), "r"((a)[2]), "r"((a)[3]), \
                   "r"((b)[0]), "r"((b)[1]))

// ---------------------------------------------------------------------------
// wsq[oc,ic] = sum_k (GAIN*w)^2
// ---------------------------------------------------------------------------
__global__ void wsq_kernel(const float* __restrict__ weight, float gain) {
    const int oc0 = blockIdx.x * 64;
    const int ic0 = blockIdx.y * 8;
    __shared__ float sw[64][73];
    for (int idx = threadIdx.x; idx < 64 * 72; idx += 256) {
        int o = idx / 72, ik = idx % 72;
        sw[o][ik] = weight[(size_t)(oc0 + o) * 4608 + ic0 * 9 + ik] * gain;
    }
    __syncthreads();
    for (int idx = threadIdx.x; idx < 64 * 8; idx += 256) {
        int o = idx >> 3, i = idx & 7;
        float s = 0.f;
#pragma unroll
        for (int k = 0; k < 9; ++k) { float v = sw[o][i * 9 + k]; s += v * v; }
        g_wsq[(oc0 + o) * NC + ic0 + i] = s;
    }
}

__global__ void sigma_kernel(const float* __restrict__ style) {
    const int b = blockIdx.y;
    const int warp = threadIdx.x >> 5, lane = threadIdx.x & 31;
    const int oc = blockIdx.x * 8 + warp;
    float v = 0.f;
    for (int i = lane; i < NC; i += 32) {
        float s = style[b * NC + i];
        v += s * s * g_wsq[oc * NC + i];
    }
#pragma unroll
    for (int off = 16; off; off >>= 1) v += __shfl_xor_sync(0xffffffffu, v, off);
    if (lane == 0) g_sigma[b * NC + oc] = rsqrtf(v + EPSV);
}

// ---------------------------------------------------------------------------
// prep: weights -> hi fp16 tiles, layout [oc(128)][k(32)] packed 64B rows.
// grid (144, 4), 256 threads: thread = (oc 0..127) x (khalf 0..1)
// ---------------------------------------------------------------------------
__global__ void prep_b(const float* __restrict__ weight, float gain) {
    const int cc = blockIdx.x, octile = blockIdx.y;
    const int icch = cc / 9, tap = cc % 9;
    const int ocl = threadIdx.x >> 1;
    const int kh = (threadIdx.x & 1) * 16;
    const int oc = octile * 128 + ocl;
    const float* wr = weight + (size_t)oc * 4608 + (size_t)(icch * 32 + kh) * 9 + tap;
    union { __half2 h2[8]; uint4 u4[2]; } H;
#pragma unroll
    for (int j = 0; j < 8; ++j) {
        float v0 = wr[(2 * j) * 9] * gain;
        float v1 = wr[(2 * j + 1) * 9] * gain;
        H.h2[j] = __halves2half2(__float2half(v0), __float2half(v1));
    }
    unsigned char* blk = g_btiles + (size_t)(octile * NCHUNK + cc) * 8192;
    uint4* dh = (uint4*)(blk + ocl * 64 + kh * 2);
    dh[0] = H.u4[0]; dh[1] = H.u4[1];
}

// ---------------------------------------------------------------------------
// conv: grid (8 pixtiles, 4 octiles, 16 b), 256 threads (8 warps).
// CTA tile: M=128 oc x N=128 pix, K-chunk 32.
// smem stage (30720B): WH[128][40]h 10240 | XH 10240 | XL 10240
// stages at 0 / 30720 ; s_sig @61440 (512B) ; s_sty @61952 (2048B)
// ---------------------------------------------------------------------------
#define RS 80u          // row stride bytes (40 halves)
#define ST_WH 0u
#define ST_XH 10240u
#define ST_XL 20480u
#define STAGE 30720u
#define SM_TOTAL 64000

__global__ void __launch_bounds__(256, 2)
conv_mma(const float* __restrict__ x, const float* __restrict__ style,
         float* __restrict__ out) {
    extern __shared__ char smem[];
    const uint32_t sb = smem_u32(smem);
    const int tid = threadIdx.x;
    const int lane = tid & 31, wid = tid >> 5;
    const int wm = wid & 1;        // m warp (oc): 0..1 -> offset wm*64
    const int wn = wid >> 1;       // n warp (pix): 0..3 -> offset wn*32
    const int pixtile = blockIdx.x, octile = blockIdx.y, b = blockIdx.z;

    float* s_sig = (float*)(smem + 61440);
    float* s_sty = (float*)(smem + 61952);
    for (int i = tid; i < 128; i += 256) s_sig[i] = g_sigma[b * NC + octile * 128 + i];
    for (int i = tid; i < NC; i += 256) s_sty[i] = style[b * NC + i];
    __syncthreads();   // s_sty must be visible to all warps before prologue storeX

    const float* xb = x + (size_t)b * NC * HW2;
    const unsigned char* wbase = g_btiles + (size_t)octile * NCHUNK * 8192;

    // per-thread build coords: p = pixel row in tile, khf = k half (0/16)
    const int p = tid >> 1;
    const int khf = (tid & 1) * 16;
    const int pr = pixtile * 4 + (p >> 5);   // image row of this pixel
    const int pc = p & 31;                   // image col

    // ldmatrix per-lane offsets
    const uint32_t aoff = (uint32_t)(lane & 15) * RS + (uint32_t)(lane >> 4) * 16u;
    const uint32_t boff = (uint32_t)(lane & 7) * RS + (uint32_t)((lane >> 3) & 1) * 16u;

    float acc[4][4][4];
#pragma unroll
    for (int m = 0; m < 4; ++m)
#pragma unroll
        for (int n = 0; n < 4; ++n)
#pragma unroll
            for (int r = 0; r < 4; ++r) acc[m][n][r] = 0.f;

    // ---- helpers ----
    auto issueW = [&](int c, uint32_t stb) {
        const unsigned char* src = wbase + (size_t)c * 8192;
#pragma unroll
        for (int j = 0; j < 2; ++j) {
            int cidx = tid + j * 256;               // 0..511 16B chunks
            int row = cidx >> 2, off = cidx & 3;
            CP_ASYNC16(sb + stb + ST_WH + row * RS + off * 16, src + cidx * 16);
        }
        CP_COMMIT();
    };
    auto prefX = [&](int c, float* xv) {
        const int icch = c / 9, tap = c - icch * 9;
        const int sr = pr + tap / 3 - 1, sc = pc + tap % 3 - 1;
        const bool inb = ((unsigned)sr < 32u) && ((unsigned)sc < 32u);
        const float* xp = xb + ((size_t)(icch * 32 + khf) << 10) +
                          (inb ? (sr * 32 + sc) : 0);
#pragma unroll
        for (int j = 0; j < 16; ++j) xv[j] = inb ? xp[(size_t)j << 10] : 0.f;
    };
    auto storeX = [&](int c, uint32_t stb, const float* xv) {
        const int icch = c / 9;
        const int styb = icch * 32 + khf;
        union { __half2 h2[8]; uint4 u4[2]; } H, L;
#pragma unroll
        for (int j = 0; j < 8; ++j) {
            float v0 = xv[2 * j] * s_sty[styb + 2 * j];
            float v1 = xv[2 * j + 1] * s_sty[styb + 2 * j + 1];
            __half h0 = __float2half(v0), h1 = __float2half(v1);
            __half l0 = __float2half(v0 - __half2float(h0));
            __half l1 = __float2half(v1 - __half2float(h1));
            H.h2[j] = __halves2half2(h0, h1);
            L.h2[j] = __halves2half2(l0, l1);
        }
        uint4* dh = (uint4*)(smem + stb + ST_XH + p * RS + khf * 2);
        uint4* dl = (uint4*)(smem + stb + ST_XL + p * RS + khf * 2);
        dh[0] = H.u4[0]; dh[1] = H.u4[1];
        dl[0] = L.u4[0]; dl[1] = L.u4[1];
    };
    // one K=32 subtile of MMAs on stage stb (kb = 0 or 32 bytes)
    auto mmaKS = [&](uint32_t stb, uint32_t kb) {
        uint32_t ah[4][4], bh[4][2], bl[4][2];
#pragma unroll
        for (int m = 0; m < 4; ++m)
            LDMX4(ah[m], sb + stb + ST_WH + (uint32_t)(wm * 64 + m * 16) * RS + kb + aoff);
#pragma unroll
        for (int n = 0; n < 4; ++n)
            LDMX2(bh[n], sb + stb + ST_XH + (uint32_t)(wn * 32 + n * 8) * RS + kb + boff);
#pragma unroll
        for (int m = 0; m < 4; ++m)
#pragma unroll
            for (int n = 0; n < 4; ++n) MMA16816(acc[m][n], ah[m], bh[n]);
#pragma unroll
        for (int n = 0; n < 4; ++n)
            LDMX2(bl[n], sb + stb + ST_XL + (uint32_t)(wn * 32 + n * 8) * RS + kb + boff);
#pragma unroll
        for (int m = 0; m < 4; ++m)
#pragma unroll
            for (int n = 0; n < 4; ++n) MMA16816(acc[m][n], ah[m], bl[n]);
    };

    // ---- prologue: chunk 0 ----
    {
        issueW(0, 0);
        float xv[16];
        prefX(0, xv);
        storeX(0, 0, xv);
        CP_WAIT0();
        __syncthreads();
    }

    // ---- main loop ----
#pragma unroll 1
    for (int c = 0; c < NCHUNK; ++c) {
        const uint32_t stb = (uint32_t)(c & 1) * STAGE;
        const uint32_t nstb = stb ^ STAGE;
        const bool more = (c + 1 < NCHUNK);
        float xv[16];
        if (more) {
            issueW(c + 1, nstb);
            prefX(c + 1, xv);
        }
        mmaKS(stb, 0u);                 // K sub-tile 0 (hides LDG latency)
        if (more) storeX(c + 1, nstb, xv);  // STS/convert overlaps tensor pipe
        mmaKS(stb, 32u);                // K sub-tile 1
        if (more) CP_WAIT0();
        __syncthreads();
    }

    // ---- epilogue: demodulate + store ----
    float* ob = out + (size_t)b * NC * HW2 + (size_t)octile * 128 * HW2 +
                pixtile * 128;
#pragma unroll
    for (int m = 0; m < 4; ++m) {
        const int r0 = wm * 64 + m * 16 + (lane >> 2);
        const float sg0 = s_sig[r0], sg1 = s_sig[r0 + 8];
#pragma unroll
        for (int n = 0; n < 4; ++n) {
            const int col = wn * 32 + n * 8 + (lane & 3) * 2;
            float2 v0 = make_float2(acc[m][n][0] * sg0, acc[m][n][1] * sg0);
            float2 v1 = make_float2(acc[m][n][2] * sg1, acc[m][n][3] * sg1);
            *(float2*)(ob + (size_t)r0 * HW2 + col) = v0;
            *(float2*)(ob + (size_t)(r0 + 8) * HW2 + col) = v1;
        }
    }
}

// ---------------------------------------------------------------------------
extern "C" void kernel_launch(void* const* d_in, const int* in_sizes, int n_in,
                              void* d_out, int out_size) {
    const float* x      = (const float*)d_in[0];
    const float* style  = (const float*)d_in[1];
    const float* weight = (const float*)d_in[2];
    float* out          = (float*)d_out;
    (void)in_sizes; (void)n_in; (void)out_size;

    const float gain = 1.0f / sqrtf(4608.0f);

    cudaFuncSetAttribute(conv_mma, cudaFuncAttributeMaxDynamicSharedMemorySize,
                         SM_TOTAL);

    wsq_kernel<<<dim3(8, 64), 256>>>(weight, gain);
    prep_b<<<dim3(NCHUNK, 4), 256>>>(weight, gain);
    sigma_kernel<<<dim3(64, 16), 256>>>(style);
    conv_mma<<<dim3(8, 4, 16), 256, SM_TOTAL>>>(x, style, out);
}